// round 7
// baseline (speedup 1.0000x reference)
#include <cuda_runtime.h>

// RWKV WKV recurrence, B=16, T=2048, D=1024 fp32, split into 4 time-chunks
// of 512 to raise occupancy from 4 to ~13 warps/SM (per-warp MLP_eff is
// scoreboard-capped ~16 lines; bandwidth scales with resident warps).
//
// State is affine in the carry: a_end = P*a_in + A with P = prod(ew).
// Kernel A: chunk 0 computed exactly (writes out + state@512), chunks 1,2
//           summarized as (P, A, B) from zero init.
// Kernel B: chunks 1..3 computed exactly, carry composed from summaries.

#define TT 2048
#define DD 1024
#define NCH 16384          // B*D channels
#define LCH 512            // chunk length
#define UU  8              // timesteps per inner block (double buffer)
#define NB  (LCH / UU)     // 64 inner blocks

// scratch: [a512 | b512 | P1 | A1 | B1 | P2 | A2 | B2], each NCH floats
__device__ float g_scr[8 * NCH];

template<int DO_OUT>
__device__ __forceinline__ void run_chunk(const float* __restrict__ kp,
                                          const float* __restrict__ vp,
                                          const float* __restrict__ wp,
                                          float* __restrict__ op,
                                          float& a, float& b, float& p)
{
    float kb[2][UU], vb[2][UU], wb[2][UU];

#pragma unroll
    for (int i = 0; i < UU; i++) {
        kb[0][i] = __ldcs(kp + i * DD);
        vb[0][i] = __ldcs(vp + i * DD);
        wb[0][i] = __ldcs(wp + i * DD);
    }

    int cur = 0;
    for (int blk = 0; blk < NB - 1; blk++) {
        const int nxt = cur ^ 1;
        const float* kq = kp + (blk + 1) * UU * DD;
        const float* vq = vp + (blk + 1) * UU * DD;
        const float* wq = wp + (blk + 1) * UU * DD;
#pragma unroll
        for (int i = 0; i < UU; i++) {
            kb[nxt][i] = __ldcs(kq + i * DD);
            vb[nxt][i] = __ldcs(vq + i * DD);
            wb[nxt][i] = __ldcs(wq + i * DD);
        }
        float* o = op + blk * UU * DD;
#pragma unroll
        for (int i = 0; i < UU; i++) {
            const float ew = __expf(wb[cur][i]);
            const float ek = __expf(kb[cur][i]);
            a = fmaf(ew, a, ek);
            b = fmaf(ew, b, ek * vb[cur][i]);
            if (DO_OUT) __stcs(o + i * DD, __fdividef(b, a));
            else        p *= ew;
        }
        cur = nxt;
    }
    // epilogue block
    float* o = op + (NB - 1) * UU * DD;
#pragma unroll
    for (int i = 0; i < UU; i++) {
        const float ew = __expf(wb[cur][i]);
        const float ek = __expf(kb[cur][i]);
        a = fmaf(ew, a, ek);
        b = fmaf(ew, b, ek * vb[cur][i]);
        if (DO_OUT) __stcs(o + i * DD, __fdividef(b, a));
        else        p *= ew;
    }
}

// Kernel A: bx<128 -> chunk0 exact; bx in [128,384) -> summaries chunk 1,2.
__global__ void __launch_bounds__(128, 1)
wkv_pass1(const float* __restrict__ k,
          const float* __restrict__ v,
          const float* __restrict__ w,
          float* __restrict__ out)
{
    const int bx = blockIdx.x;
    float a = 0.0f, b = 0.0f, p = 1.0f;

    if (bx < 128) {
        const int ch = bx * 128 + threadIdx.x;
        const long base = (long)(ch >> 10) * TT * DD + (ch & (DD - 1));
        run_chunk<1>(k + base, v + base, w + base, out + base, a, b, p);
        g_scr[0 * NCH + ch] = a;     // state a @ t=512
        g_scr[1 * NCH + ch] = b;     // state b @ t=512
    } else {
        const int j = 1 + ((bx - 128) >> 7);        // chunk 1 or 2
        const int ch = ((bx - 128) & 127) * 128 + threadIdx.x;
        const long base = (long)(ch >> 10) * TT * DD + (ch & (DD - 1))
                        + (long)j * LCH * DD;
        run_chunk<0>(k + base, v + base, w + base, (float*)nullptr, a, b, p);
        const int s = 2 + (j - 1) * 3;              // P1@2 or P2@5
        g_scr[(s + 0) * NCH + ch] = p;
        g_scr[(s + 1) * NCH + ch] = a;
        g_scr[(s + 2) * NCH + ch] = b;
    }
}

// Kernel B: chunks 1..3 exact, carry-in composed from scratch.
__global__ void __launch_bounds__(128, 1)
wkv_pass2(const float* __restrict__ k,
          const float* __restrict__ v,
          const float* __restrict__ w,
          float* __restrict__ out)
{
    const int bx = blockIdx.x;
    const int j  = 1 + (bx >> 7);                   // chunk 1..3
    const int ch = (bx & 127) * 128 + threadIdx.x;

    float a = g_scr[0 * NCH + ch];                  // state @ t=512
    float b = g_scr[1 * NCH + ch];
    if (j >= 2) {                                   // advance to t=1024
        const float P = g_scr[2 * NCH + ch];
        a = fmaf(P, a, g_scr[3 * NCH + ch]);
        b = fmaf(P, b, g_scr[4 * NCH + ch]);
    }
    if (j == 3) {                                   // advance to t=1536
        const float P = g_scr[5 * NCH + ch];
        a = fmaf(P, a, g_scr[6 * NCH + ch]);
        b = fmaf(P, b, g_scr[7 * NCH + ch]);
    }

    const long base = (long)(ch >> 10) * TT * DD + (ch & (DD - 1))
                    + (long)j * LCH * DD;
    float p = 1.0f;
    run_chunk<1>(k + base, v + base, w + base, out + base, a, b, p);
}

extern "C" void kernel_launch(void* const* d_in, const int* in_sizes, int n_in,
                              void* d_out, int out_size)
{
    const float* k = (const float*)d_in[0];
    const float* v = (const float*)d_in[1];
    const float* w = (const float*)d_in[2];
    float* out = (float*)d_out;

    wkv_pass1<<<384, 128>>>(k, v, w, out);   // chunk0 exact + summaries 1,2
    wkv_pass2<<<384, 128>>>(k, v, w, out);   // chunks 1..3 exact
}